// round 8
// baseline (speedup 1.0000x reference)
#include <cuda_runtime.h>
#include <cuda_bf16.h>
#include <stdint.h>
#include <math.h>

#define NBATCH 4
#define NFQ    300
#define QDIM   512
#define HIDDEN 512
#define NHEADS 8
#define HD     64
#define NPIX   6400
#define NORMF  0.125f
#define MROWS  (NBATCH*NFQ)          // 1200
#define OROWS  (NFQ*NHEADS)          // 2400
#define CBLK_PER_BATCH 1200          // 8 heads * 3 mtiles * 50 ntiles

// ---------------- static device scratch ----------------
__device__ __nv_bfloat16 g_kw_hi[HIDDEN*QDIM];
__device__ __nv_bfloat16 g_kw_lo[HIDDEN*QDIM];
__device__ __nv_bfloat16 g_kt_hi[(size_t)NBATCH*NPIX*QDIM];   // [b][p][d]
__device__ __nv_bfloat16 g_kt_lo[(size_t)NBATCH*NPIX*QDIM];
__device__ __nv_bfloat16 g_qht_hi[NBATCH*NHEADS*NFQ*HD];      // [b][n][f][c]
__device__ __nv_bfloat16 g_qht_lo[NBATCH*NHEADS*NFQ*HD];
__device__ __nv_bfloat16 g_kpt_hi[(size_t)NBATCH*NHEADS*NPIX*HD]; // [b][n][p][c]
__device__ __nv_bfloat16 g_kpt_lo[(size_t)NBATCH*NHEADS*NPIX*HD];
__device__ float g_pmax[NBATCH*CBLK_PER_BATCH];
__device__ float g_psum[NBATCH*CBLK_PER_BATCH];
__device__ float g_M[NBATCH];
__device__ float g_invZ[NBATCH];

// ---------------- smem layout ----------------
// fused tiles: one 128-row x 128-byte tile holds hi (bytes 0..63) | lo (64..127)
// stage: A-tile 16KB + B-tile 16KB = 32KB; 3 stages
#define STAGE_SZ 32768u
#define STG(s)   ((uint32_t)(s) * STAGE_SZ)
#define C_OFF  0u                        // fp32 [128][132] overlay: 67584 B (aliases stages)
#define KB_OFF 98304u                    // kproj bias (512 B)
#define RM_OFF 98304u                    // scores reduce max (1024 B)
#define RS_OFF 99328u                    // scores reduce sum (1024 B)
#define MK_OFF 100352u                   // scores mask tile (512 B)
#define SMEM_SZ 100864u

// ---------------- ptx helpers ----------------
__device__ __forceinline__ uint32_t smem_u32(const void* p) {
    uint32_t a;
    asm("{ .reg .u64 t; cvta.to.shared.u64 t, %1; cvt.u32.u64 %0, t; }" : "=r"(a) : "l"(p));
    return a;
}
__device__ __forceinline__ void cpa16(uint32_t dst, const void* src, int srcbytes) {
    asm volatile("cp.async.cg.shared.global [%0], [%1], 16, %2;"
                 :: "r"(dst), "l"(src), "r"(srcbytes) : "memory");
}
#define CP_COMMIT() asm volatile("cp.async.commit_group;" ::: "memory")
#define CP_WAIT1()  asm volatile("cp.async.wait_group 1;" ::: "memory")
#define CP_WAIT0()  asm volatile("cp.async.wait_group 0;" ::: "memory")

__device__ __forceinline__ void ldm_x4(uint32_t& r0, uint32_t& r1, uint32_t& r2, uint32_t& r3,
                                       uint32_t addr) {
    asm volatile("ldmatrix.sync.aligned.m8n8.x4.shared.b16 {%0,%1,%2,%3}, [%4];"
                 : "=r"(r0), "=r"(r1), "=r"(r2), "=r"(r3) : "r"(addr));
}
__device__ __forceinline__ void mma_bf16(float* c, uint32_t a0, uint32_t a1, uint32_t a2,
                                         uint32_t a3, uint32_t b0, uint32_t b1) {
    asm volatile("mma.sync.aligned.m16n8k16.row.col.f32.bf16.bf16.f32 "
        "{%0,%1,%2,%3}, {%4,%5,%6,%7}, {%8,%9}, {%0,%1,%2,%3};"
        : "+f"(c[0]), "+f"(c[1]), "+f"(c[2]), "+f"(c[3])
        : "r"(a0), "r"(a1), "r"(a2), "r"(a3), "r"(b0), "r"(b1));
}
__device__ __forceinline__ uint32_t sw128(uint32_t off) { return off ^ ((off >> 3) & 0x70); }

__device__ __forceinline__ void split_bf16(float x, __nv_bfloat16& h, __nv_bfloat16& l) {
    h = __float2bfloat16(x);
    l = __float2bfloat16(x - __bfloat162float(h));
}

// ---- load fused hi|lo tile: 128 rows x (32 hi bf16 | 32 lo bf16) = 16KB ----
// thread t: row = t>>1, half = t&1 (0=hi from baseHi, 1=lo from baseLo)
__device__ __forceinline__ void load_tile32(uint32_t dst,
                                            const __nv_bfloat16* baseHi,
                                            const __nv_bfloat16* baseLo,
                                            int rowstride, int k0, int t, int nrows) {
    int r = t >> 1, half = t & 1;
    const __nv_bfloat16* base = half ? baseLo : baseHi;
    int rc = (r < nrows) ? r : 0;
    const char* src = (const char*)(base + (size_t)rc*rowstride + k0);
    int ok = (r < nrows) ? 16 : 0;
#pragma unroll
    for (int j = 0; j < 4; j++) {
        uint32_t off = sw128((uint32_t)(r*128 + half*64 + j*16));
        cpa16(dst + off, src + j*16, ok);
    }
}

// ---- fused 3-term compute on a 32-wide K chunk (warp tile 64x32) ----
// per k16: Ah(4 ldm)+Bh(2 ldm) -> 16 HMMA; Bl(2) -> 16 HMMA; Al(4) -> 16 HMMA
__device__ __forceinline__ void compute_chunk32(uint32_t aB, uint32_t bB,
                                                int wm, int wn, int lane,
                                                float acc[4][4][4]) {
#pragma unroll
    for (int kk = 0; kk < 32; kk += 16) {
        int arow_b = (wm*64 + (lane & 15)) * 128 + (kk + ((lane >> 4) << 3)) * 2;
        int brow_b = (wn*32 + ((lane >> 4) << 3) + (lane & 7)) * 128
                   + (kk + (((lane >> 3) & 1) << 3)) * 2;
        uint32_t ah[4][4];
#pragma unroll
        for (int mf = 0; mf < 4; mf++)
            ldm_x4(ah[mf][0], ah[mf][1], ah[mf][2], ah[mf][3],
                   aB + sw128((uint32_t)(arow_b + mf*16*128)));
        uint32_t bh[4][2];
#pragma unroll
        for (int g = 0; g < 2; g++) {
            uint32_t r0, r1, r2, r3;
            ldm_x4(r0, r1, r2, r3, bB + sw128((uint32_t)(brow_b + g*16*128)));
            bh[g*2][0] = r0; bh[g*2][1] = r1; bh[g*2+1][0] = r2; bh[g*2+1][1] = r3;
        }
#pragma unroll
        for (int mf = 0; mf < 4; mf++)
#pragma unroll
            for (int nf = 0; nf < 4; nf++)
                mma_bf16(acc[mf][nf], ah[mf][0], ah[mf][1], ah[mf][2], ah[mf][3],
                         bh[nf][0], bh[nf][1]);
        uint32_t bl[4][2];
#pragma unroll
        for (int g = 0; g < 2; g++) {
            uint32_t r0, r1, r2, r3;
            ldm_x4(r0, r1, r2, r3, bB + sw128((uint32_t)(brow_b + 64 + g*16*128)));
            bl[g*2][0] = r0; bl[g*2][1] = r1; bl[g*2+1][0] = r2; bl[g*2+1][1] = r3;
        }
#pragma unroll
        for (int mf = 0; mf < 4; mf++)
#pragma unroll
            for (int nf = 0; nf < 4; nf++)
                mma_bf16(acc[mf][nf], ah[mf][0], ah[mf][1], ah[mf][2], ah[mf][3],
                         bl[nf][0], bl[nf][1]);
        uint32_t al[4][4];
#pragma unroll
        for (int mf = 0; mf < 4; mf++)
            ldm_x4(al[mf][0], al[mf][1], al[mf][2], al[mf][3],
                   aB + sw128((uint32_t)(arow_b + 64 + mf*16*128)));
#pragma unroll
        for (int mf = 0; mf < 4; mf++)
#pragma unroll
            for (int nf = 0; nf < 4; nf++)
                mma_bf16(acc[mf][nf], al[mf][0], al[mf][1], al[mf][2], al[mf][3],
                         bh[nf][0], bh[nf][1]);
    }
}

// ============================================================
// convert kw -> bf16 hi/lo
// ============================================================
__global__ void kwconv_kernel(const float* __restrict__ kw) {
    int n = HIDDEN*QDIM;
    for (int i = blockIdx.x*blockDim.x + threadIdx.x; i < n; i += gridDim.x*blockDim.x) {
        __nv_bfloat16 h, l; split_bf16(kw[i], h, l);
        g_kw_hi[i] = h; g_kw_lo[i] = l;
    }
}

// ============================================================
// convert + transpose k: [b][d][p] fp32 -> [b][p][d] bf16 hi/lo
// ============================================================
__global__ void kconv_kernel(const float* __restrict__ kin) {
    __shared__ float tile[32][33];
    int b = blockIdx.z;
    int p0 = blockIdx.x*32, d0 = blockIdx.y*32;
    int tx = threadIdx.x, ty = threadIdx.y;
    const float* src = kin + ((size_t)b*QDIM + d0)*NPIX + p0;
#pragma unroll
    for (int i = 0; i < 4; i++)
        tile[ty + i*8][tx] = src[(size_t)(ty + i*8)*NPIX + tx];
    __syncthreads();
#pragma unroll
    for (int i = 0; i < 4; i++) {
        int pl = ty + i*8;
        float x = tile[tx][pl];
        __nv_bfloat16 h, l; split_bf16(x, h, l);
        size_t o = ((size_t)b*NPIX + p0 + pl)*QDIM + d0 + tx;
        g_kt_hi[o] = h; g_kt_lo[o] = l;
    }
}

// ============================================================
// q projection (SIMT) -> qht hi/lo [b][n][f][c]
// ============================================================
__global__ void qproj_kernel(const float* __restrict__ q,
                             const float* __restrict__ qw,
                             const float* __restrict__ qb) {
    const int BM = 64, BN = 64, BK = 16;
    __shared__ float As[BK][BM];
    __shared__ float Bs[BK][BN];
    int t  = threadIdx.x;
    int tx = t & 15, ty = t >> 4;
    int m0 = blockIdx.y * BM;
    int n0 = blockIdx.x * BN;
    int lrow = t >> 2, lseg = t & 3;

    float acc[4][4] = {};
    for (int k0 = 0; k0 < QDIM; k0 += BK) {
        float4 av = make_float4(0.f, 0.f, 0.f, 0.f);
        int gm = m0 + lrow;
        if (gm < MROWS)
            av = *(const float4*)(q + (size_t)gm*QDIM + k0 + lseg*4);
        float4 bv = *(const float4*)(qw + (size_t)(n0 + lrow)*QDIM + k0 + lseg*4);
        __syncthreads();
        As[lseg*4+0][lrow]=av.x; As[lseg*4+1][lrow]=av.y;
        As[lseg*4+2][lrow]=av.z; As[lseg*4+3][lrow]=av.w;
        Bs[lseg*4+0][lrow]=bv.x; Bs[lseg*4+1][lrow]=bv.y;
        Bs[lseg*4+2][lrow]=bv.z; Bs[lseg*4+3][lrow]=bv.w;
        __syncthreads();
#pragma unroll
        for (int k = 0; k < BK; k++) {
            float a[4], b[4];
            *(float4*)a = *(float4*)&As[k][ty*4];
            *(float4*)b = *(float4*)&Bs[k][tx*4];
#pragma unroll
            for (int i = 0; i < 4; i++)
#pragma unroll
                for (int j = 0; j < 4; j++)
                    acc[i][j] += a[i]*b[j];
        }
    }
#pragma unroll
    for (int i = 0; i < 4; i++) {
        int gm = m0 + ty*4 + i;
        if (gm >= MROWS) continue;
        int b = gm / NFQ, f = gm % NFQ;
#pragma unroll
        for (int j = 0; j < 4; j++) {
            int e = n0 + tx*4 + j;
            int n = e >> 6, c = e & 63;
            float x = (acc[i][j] + qb[e]) * NORMF;
            __nv_bfloat16 h, l; split_bf16(x, h, l);
            size_t o = (((size_t)(b*NHEADS + n))*NFQ + f)*HD + c;
            g_qht_hi[o] = h; g_qht_lo[o] = l;
        }
    }
}

// ============================================================
// kproj HMMA (fused 3-term, 3-stage): C[e,p] = sum_d kw[e,d]*kt[p,d] + kb[e]
// grid (50 p, 4 e, 4 b), 256 thr
// ============================================================
__global__ void __launch_bounds__(256, 2) kproj_mma_kernel(const float* __restrict__ kb) {
    extern __shared__ char smem[];
    uint32_t sb = smem_u32(smem);
    int t = threadIdx.x, lane = t & 31, w = t >> 5, wm = w >> 2, wn = w & 3;
    int b = blockIdx.z;
    int e0 = blockIdx.y * 128;
    int p0 = blockIdx.x * 128;

    const __nv_bfloat16* AHi = g_kw_hi + (size_t)e0*QDIM;
    const __nv_bfloat16* ALo = g_kw_lo + (size_t)e0*QDIM;
    const __nv_bfloat16* BHi = g_kt_hi + ((size_t)b*NPIX + p0)*QDIM;
    const __nv_bfloat16* BLo = g_kt_lo + ((size_t)b*NPIX + p0)*QDIM;

    float acc[4][4][4] = {};
    const int ITERS = 16;   // K=512 in 32-wide fused chunks

    load_tile32(sb + STG(0),          AHi, ALo, QDIM, 0, t, 128);
    load_tile32(sb + STG(0) + 16384u, BHi, BLo, QDIM, 0, t, 128);
    CP_COMMIT();
    load_tile32(sb + STG(1),          AHi, ALo, QDIM, 32, t, 128);
    load_tile32(sb + STG(1) + 16384u, BHi, BLo, QDIM, 32, t, 128);
    CP_COMMIT();

    int stage = 0, nstage = 2;
    for (int it = 0; it < ITERS; it++) {
        if (it == ITERS - 1) { CP_WAIT0(); } else { CP_WAIT1(); }
        __syncthreads();
        if (it + 2 < ITERS) {
            int k0 = (it + 2) * 32;
            load_tile32(sb + STG(nstage),          AHi, ALo, QDIM, k0, t, 128);
            load_tile32(sb + STG(nstage) + 16384u, BHi, BLo, QDIM, k0, t, 128);
            CP_COMMIT();
        }
        compute_chunk32(sb + STG(stage), sb + STG(stage) + 16384u, wm, wn, lane, acc);
        stage = (stage + 1 == 3) ? 0 : stage + 1;
        nstage = (nstage + 1 == 3) ? 0 : nstage + 1;
    }
    __syncthreads();   // protect C overlay (aliases stage buffers)

    float* Cs = (float*)(smem + C_OFF);
    float* kbs = (float*)(smem + KB_OFF);
    if (t < 128) kbs[t] = kb[e0 + t];
    __syncthreads();
#pragma unroll
    for (int mf = 0; mf < 4; mf++) {
        int e = wm*64 + mf*16 + (lane >> 2);
        float b0 = kbs[e], b1 = kbs[e + 8];
#pragma unroll
        for (int nf = 0; nf < 4; nf++) {
            int p = wn*32 + nf*8 + (lane & 3)*2;
            Cs[e*132 + p]       = acc[mf][nf][0] + b0;
            Cs[e*132 + p + 1]   = acc[mf][nf][1] + b0;
            Cs[(e+8)*132 + p]   = acc[mf][nf][2] + b1;
            Cs[(e+8)*132 + p+1] = acc[mf][nf][3] + b1;
        }
    }
    __syncthreads();
    {
        int pl = t & 127, hd = t >> 7;
        size_t rowbase = (((size_t)(b*NHEADS) + blockIdx.y*2 + hd)*NPIX + p0 + pl)*HD;
#pragma unroll
        for (int c8 = 0; c8 < 8; c8++) {
            __align__(16) __nv_bfloat16 h8[8];
            __align__(16) __nv_bfloat16 l8[8];
#pragma unroll
            for (int j = 0; j < 8; j++) {
                float x = Cs[(hd*64 + c8*8 + j)*132 + pl];
                split_bf16(x, h8[j], l8[j]);
            }
            *(uint4*)(g_kpt_hi + rowbase + c8*8) = *(uint4*)h8;
            *(uint4*)(g_kpt_lo + rowbase + c8*8) = *(uint4*)l8;
        }
    }
}

// ============================================================
// scores HMMA (fused 3-term): S[f,p] = sum_c qht·kpt
// + mask + block softmax stats + store.  grid (50 p, 3 f, 32 bh)
// ============================================================
__global__ void __launch_bounds__(256, 2) scores_mma_kernel(const int* __restrict__ mask,
                                                            float* __restrict__ out) {
    extern __shared__ char smem[];
    uint32_t sb = smem_u32(smem);
    int t = threadIdx.x, lane = t & 31, w = t >> 5, wm = w >> 2, wn = w & 3;
    int bh = blockIdx.z;
    int b = bh >> 3, n = bh & 7;
    int m0 = blockIdx.y * 128;
    int p0 = blockIdx.x * 128;

    int* mS = (int*)(smem + MK_OFF);
    if (t < 128) mS[t] = mask[(size_t)b*NPIX + p0 + t];

    int nrows = NFQ - m0; if (nrows > 128) nrows = 128;
    const __nv_bfloat16* AHi = g_qht_hi + (((size_t)(b*NHEADS + n))*NFQ + m0)*HD;
    const __nv_bfloat16* ALo = g_qht_lo + (((size_t)(b*NHEADS + n))*NFQ + m0)*HD;
    const __nv_bfloat16* BHi = g_kpt_hi + (((size_t)(b*NHEADS + n))*NPIX + p0)*HD;
    const __nv_bfloat16* BLo = g_kpt_lo + (((size_t)(b*NHEADS + n))*NPIX + p0)*HD;

    float acc[4][4][4] = {};
    load_tile32(sb + STG(0),          AHi, ALo, HD, 0, t, nrows);
    load_tile32(sb + STG(0) + 16384u, BHi, BLo, HD, 0, t, 128);
    CP_COMMIT();
    load_tile32(sb + STG(1),          AHi, ALo, HD, 32, t, nrows);
    load_tile32(sb + STG(1) + 16384u, BHi, BLo, HD, 32, t, 128);
    CP_COMMIT();
    CP_WAIT1();
    __syncthreads();
    compute_chunk32(sb + STG(0), sb + STG(0) + 16384u, wm, wn, lane, acc);
    CP_WAIT0();
    __syncthreads();
    compute_chunk32(sb + STG(1), sb + STG(1) + 16384u, wm, wn, lane, acc);

    // ---- epilogue: mask + store + thread-local stats (from registers) ----
    float* rm = (float*)(smem + RM_OFF);
    float* rs = (float*)(smem + RS_OFF);
    size_t obase = (size_t)b*OROWS*NPIX;
    float tmax = -INFINITY;
#pragma unroll
    for (int mf = 0; mf < 4; mf++) {
        int fl = wm*64 + mf*16 + (lane >> 2);
#pragma unroll
        for (int half = 0; half < 2; half++) {
            int fg = m0 + fl + half*8;
            if (fg < NFQ) {
                size_t rowb = obase + ((size_t)fg*NHEADS + n)*NPIX + p0;
#pragma unroll
                for (int nf = 0; nf < 4; nf++) {
                    int nc = wn*32 + nf*8 + (lane & 3)*2;
                    float v0 = mS[nc]   ? -INFINITY : acc[mf][nf][half*2];
                    float v1 = mS[nc+1] ? -INFINITY : acc[mf][nf][half*2+1];
                    *(float2*)(out + rowb + nc) = make_float2(v0, v1);
                    tmax = fmaxf(tmax, fmaxf(v0, v1));
                }
            }
        }
    }
    float tsum = 0.f;
    if (tmax > -1e37f) {
#pragma unroll
        for (int mf = 0; mf < 4; mf++) {
            int fl = wm*64 + mf*16 + (lane >> 2);
#pragma unroll
            for (int half = 0; half < 2; half++) {
                int fg = m0 + fl + half*8;
                if (fg < NFQ) {
#pragma unroll
                    for (int nf = 0; nf < 4; nf++) {
                        int nc = wn*32 + nf*8 + (lane & 3)*2;
                        if (!mS[nc])   tsum += __expf(acc[mf][nf][half*2]   - tmax);
                        if (!mS[nc+1]) tsum += __expf(acc[mf][nf][half*2+1] - tmax);
                    }
                }
            }
        }
    }
    rm[t] = tmax; rs[t] = tsum;
    __syncthreads();
    for (int s = 128; s > 0; s >>= 1) {
        if (t < s) {
            float m1 = rm[t], s1v = rs[t];
            float m2 = rm[t+s], s2v = rs[t+s];
            float M = fmaxf(m1, m2);
            float sum = 0.f;
            if (m1 > -1e37f) sum += s1v * __expf(m1 - M);
            if (m2 > -1e37f) sum += s2v * __expf(m2 - M);
            rm[t] = M; rs[t] = sum;
        }
        __syncthreads();
    }
    if (t == 0) {
        int pidx = (int)blockIdx.z*150 + (int)blockIdx.y*50 + (int)blockIdx.x;
        g_pmax[pidx] = rm[0];
        g_psum[pidx] = rs[0];
    }
}

// ============================================================
// combine per-block stats -> per-batch (M, 1/Z)
// ============================================================
__global__ void combine_kernel() {
    __shared__ float rm[256];
    __shared__ float rs[256];
    int b = blockIdx.x, t = threadIdx.x;
    float m = -INFINITY, s = 0.f;
    for (int i = t; i < CBLK_PER_BATCH; i += 256) {
        float m2 = g_pmax[b*CBLK_PER_BATCH + i];
        float s2 = g_psum[b*CBLK_PER_BATCH + i];
        float M = fmaxf(m, m2);
        float ns = 0.f;
        if (m  > -1e37f) ns += s  * __expf(m  - M);
        if (m2 > -1e37f) ns += s2 * __expf(m2 - M);
        m = M; s = ns;
    }
    rm[t] = m; rs[t] = s;
    __syncthreads();
    for (int st = 128; st > 0; st >>= 1) {
        if (t < st) {
            float m1 = rm[t], s1v = rs[t];
            float m2 = rm[t+st], s2v = rs[t+st];
            float M = fmaxf(m1, m2);
            float sum = 0.f;
            if (m1 > -1e37f) sum += s1v * __expf(m1 - M);
            if (m2 > -1e37f) sum += s2v * __expf(m2 - M);
            rm[t] = M; rs[t] = sum;
        }
        __syncthreads();
    }
    if (t == 0) {
        g_M[b] = rm[0];
        g_invZ[b] = 1.0f / rs[0];
    }
}

// ============================================================
// normalize in place
// ============================================================
__global__ void norm_kernel(float* __restrict__ out) {
    const int VPB = (OROWS*NPIX) / 4;
    const int NV  = NBATCH * VPB;
    float4* o = (float4*)out;
    for (int i = blockIdx.x*blockDim.x + threadIdx.x; i < NV;
         i += gridDim.x*blockDim.x) {
        int b = i / VPB;
        float M  = g_M[b];
        float iz = g_invZ[b];
        float4 v = o[i];
        v.x = (v.x > -1e37f) ? __expf(v.x - M)*iz : 0.f;
        v.y = (v.y > -1e37f) ? __expf(v.y - M)*iz : 0.f;
        v.z = (v.z > -1e37f) ? __expf(v.z - M)*iz : 0.f;
        v.w = (v.w > -1e37f) ? __expf(v.w - M)*iz : 0.f;
        o[i] = v;
    }
}

// ============================================================
extern "C" void kernel_launch(void* const* d_in, const int* in_sizes, int n_in,
                              void* d_out, int out_size) {
    const float* q    = (const float*)d_in[0];
    const float* k    = (const float*)d_in[1];
    const int*   mask = (const int*)  d_in[2];
    const float* qw   = (const float*)d_in[3];
    const float* qb   = (const float*)d_in[4];
    const float* kw   = (const float*)d_in[5];
    const float* kb   = (const float*)d_in[6];
    float* out = (float*)d_out;

    cudaFuncSetAttribute(kproj_mma_kernel,  cudaFuncAttributeMaxDynamicSharedMemorySize, SMEM_SZ);
    cudaFuncSetAttribute(scores_mma_kernel, cudaFuncAttributeMaxDynamicSharedMemorySize, SMEM_SZ);

    kwconv_kernel <<<256, 256>>>(kw);
    kconv_kernel  <<<dim3(200, 16, 4), dim3(32, 8)>>>(k);
    qproj_kernel  <<<dim3(8, 19), 256>>>(q, qw, qb);
    kproj_mma_kernel <<<dim3(50, 4, 4),  256, SMEM_SZ>>>(kb);
    scores_mma_kernel<<<dim3(50, 3, 32), 256, SMEM_SZ>>>(mask, out);
    combine_kernel<<<4, 256>>>();
    norm_kernel   <<<2048, 256>>>(out);
}

// round 10
// speedup vs baseline: 1.0913x; 1.0913x over previous
#include <cuda_runtime.h>
#include <cuda_bf16.h>
#include <stdint.h>
#include <math.h>

#define NBATCH 4
#define NFQ    300
#define QDIM   512
#define HIDDEN 512
#define NHEADS 8
#define HD     64
#define NPIX   6400
#define NORMF  0.125f
#define MROWS  (NBATCH*NFQ)          // 1200
#define OROWS  (NFQ*NHEADS)          // 2400
#define CBLK_PER_BATCH 1200          // 8 heads * 3 mtiles * 50 ntiles

// ---------------- static device scratch ----------------
__device__ __nv_bfloat16 g_kw_hi[HIDDEN*QDIM];
__device__ __nv_bfloat16 g_kw_lo[HIDDEN*QDIM];
__device__ __nv_bfloat16 g_kt_hi[(size_t)NBATCH*NPIX*QDIM];   // [b][p][d]
__device__ __nv_bfloat16 g_kt_lo[(size_t)NBATCH*NPIX*QDIM];
__device__ __nv_bfloat16 g_qht_hi[NBATCH*NHEADS*NFQ*HD];      // [b][n][f][c]
__device__ __nv_bfloat16 g_qht_lo[NBATCH*NHEADS*NFQ*HD];
__device__ __nv_bfloat16 g_kpt_hi[(size_t)NBATCH*NHEADS*NPIX*HD]; // [b][n][p][c]
__device__ __nv_bfloat16 g_kpt_lo[(size_t)NBATCH*NHEADS*NPIX*HD];
__device__ float g_pmax[NBATCH*CBLK_PER_BATCH];
__device__ float g_psum[NBATCH*CBLK_PER_BATCH];
__device__ float g_bscale[NBATCH*CBLK_PER_BATCH];

// ---------------- smem layout (bytes into dynamic smem) ----------------
// 3 stages, each: A tile 16KB + B tile 16KB = 32KB
#define STAGE_SZ 32768u
#define STG(s)   ((uint32_t)(s) * STAGE_SZ)
#define C_OFF  0u                        // fp32 [128][132] overlay after compute: 67584 B
#define KB_OFF 98304u                    // kproj: bias tile (512 B)
#define RM_OFF 98304u                    // scores: reduce max (1024 B)
#define RS_OFF 99328u                    // scores: reduce sum (1024 B)
#define MK_OFF 100352u                   // scores: mask tile (512 B)
#define SMEM_SZ 100864u

// ---------------- ptx helpers ----------------
__device__ __forceinline__ uint32_t smem_u32(const void* p) {
    uint32_t a;
    asm("{ .reg .u64 t; cvta.to.shared.u64 t, %1; cvt.u32.u64 %0, t; }" : "=r"(a) : "l"(p));
    return a;
}
__device__ __forceinline__ void cpa16(uint32_t dst, const void* src, int srcbytes) {
    asm volatile("cp.async.cg.shared.global [%0], [%1], 16, %2;"
                 :: "r"(dst), "l"(src), "r"(srcbytes) : "memory");
}
#define CP_COMMIT() asm volatile("cp.async.commit_group;" ::: "memory")
#define CP_WAIT1()  asm volatile("cp.async.wait_group 1;" ::: "memory")
#define CP_WAIT0()  asm volatile("cp.async.wait_group 0;" ::: "memory")

__device__ __forceinline__ void ldm_x4(uint32_t& r0, uint32_t& r1, uint32_t& r2, uint32_t& r3,
                                       uint32_t addr) {
    asm volatile("ldmatrix.sync.aligned.m8n8.x4.shared.b16 {%0,%1,%2,%3}, [%4];"
                 : "=r"(r0), "=r"(r1), "=r"(r2), "=r"(r3) : "r"(addr));
}
__device__ __forceinline__ void mma_bf16(float* c, uint32_t a0, uint32_t a1, uint32_t a2,
                                         uint32_t a3, uint32_t b0, uint32_t b1) {
    asm volatile("mma.sync.aligned.m16n8k16.row.col.f32.bf16.bf16.f32 "
        "{%0,%1,%2,%3}, {%4,%5,%6,%7}, {%8,%9}, {%0,%1,%2,%3};"
        : "+f"(c[0]), "+f"(c[1]), "+f"(c[2]), "+f"(c[3])
        : "r"(a0), "r"(a1), "r"(a2), "r"(a3), "r"(b0), "r"(b1));
}
__device__ __forceinline__ uint32_t sw128(uint32_t off) { return off ^ ((off >> 3) & 0x70); }

__device__ __forceinline__ void split_bf16(float x, __nv_bfloat16& h, __nv_bfloat16& l) {
    h = __float2bfloat16(x);
    l = __float2bfloat16(x - __bfloat162float(h));
}

// ---- load a [128 rows x 64 bf16] tile into swizzled smem via cp.async ----
__device__ __forceinline__ void load_tile64(uint32_t dst, const __nv_bfloat16* base,
                                            int rowstride, int k0, int t, int nrows) {
    int r = t >> 1, half = t & 1;
    int rc = (r < nrows) ? r : 0;
    const char* src = (const char*)(base + (size_t)rc*rowstride + k0 + half*32);
    int ok = (r < nrows) ? 16 : 0;
#pragma unroll
    for (int j = 0; j < 4; j++) {
        uint32_t off = sw128((uint32_t)(r*128 + half*64 + j*16));
        cpa16(dst + off, src + j*16, ok);
    }
}

// ---- one 64-wide K chunk of 128x128 HMMA (warp tile 64x32) ----
__device__ __forceinline__ void compute_chunk(uint32_t aBase, uint32_t bBase,
                                              int wm, int wn, int lane,
                                              float acc[4][4][4]) {
#pragma unroll
    for (int kk = 0; kk < 64; kk += 16) {
        uint32_t a[4][4];
#pragma unroll
        for (int mf = 0; mf < 4; mf++) {
            int row  = wm*64 + mf*16 + (lane & 15);
            int kcol = kk + ((lane >> 4) << 3);
            uint32_t off = sw128((uint32_t)(row*128 + kcol*2));
            ldm_x4(a[mf][0], a[mf][1], a[mf][2], a[mf][3], aBase + off);
        }
        uint32_t b[4][2];
#pragma unroll
        for (int g = 0; g < 2; g++) {
            int nrow = wn*32 + g*16 + ((lane >> 4) << 3) + (lane & 7);
            int kcol = kk + (((lane >> 3) & 1) << 3);
            uint32_t off = sw128((uint32_t)(nrow*128 + kcol*2));
            uint32_t r0, r1, r2, r3;
            ldm_x4(r0, r1, r2, r3, bBase + off);
            b[g*2][0] = r0; b[g*2][1] = r1; b[g*2+1][0] = r2; b[g*2+1][1] = r3;
        }
#pragma unroll
        for (int mf = 0; mf < 4; mf++)
#pragma unroll
            for (int nf = 0; nf < 4; nf++)
                mma_bf16(acc[mf][nf], a[mf][0], a[mf][1], a[mf][2], a[mf][3],
                         b[nf][0], b[nf][1]);
    }
}

// ============================================================
// convert kw -> bf16 hi/lo
// ============================================================
__global__ void kwconv_kernel(const float* __restrict__ kw) {
    int n = HIDDEN*QDIM;
    for (int i = blockIdx.x*blockDim.x + threadIdx.x; i < n; i += gridDim.x*blockDim.x) {
        __nv_bfloat16 h, l; split_bf16(kw[i], h, l);
        g_kw_hi[i] = h; g_kw_lo[i] = l;
    }
}

// ============================================================
// convert + transpose k: [b][d][p] fp32 -> [b][p][d] bf16 hi/lo
// ============================================================
__global__ void kconv_kernel(const float* __restrict__ kin) {
    __shared__ float tile[32][33];
    int b = blockIdx.z;
    int p0 = blockIdx.x*32, d0 = blockIdx.y*32;
    int tx = threadIdx.x, ty = threadIdx.y;
    const float* src = kin + ((size_t)b*QDIM + d0)*NPIX + p0;
#pragma unroll
    for (int i = 0; i < 4; i++)
        tile[ty + i*8][tx] = src[(size_t)(ty + i*8)*NPIX + tx];
    __syncthreads();
#pragma unroll
    for (int i = 0; i < 4; i++) {
        int pl = ty + i*8;
        float x = tile[tx][pl];
        __nv_bfloat16 h, l; split_bf16(x, h, l);
        size_t o = ((size_t)b*NPIX + p0 + pl)*QDIM + d0 + tx;
        g_kt_hi[o] = h; g_kt_lo[o] = l;
    }
}

// ============================================================
// q projection (SIMT) -> qht hi/lo [b][n][f][c]
// ============================================================
__global__ void qproj_kernel(const float* __restrict__ q,
                             const float* __restrict__ qw,
                             const float* __restrict__ qb) {
    const int BM = 64, BN = 64, BK = 16;
    __shared__ float As[BK][BM];
    __shared__ float Bs[BK][BN];
    int t  = threadIdx.x;
    int tx = t & 15, ty = t >> 4;
    int m0 = blockIdx.y * BM;
    int n0 = blockIdx.x * BN;
    int lrow = t >> 2, lseg = t & 3;

    float acc[4][4] = {};
    for (int k0 = 0; k0 < QDIM; k0 += BK) {
        float4 av = make_float4(0.f, 0.f, 0.f, 0.f);
        int gm = m0 + lrow;
        if (gm < MROWS)
            av = *(const float4*)(q + (size_t)gm*QDIM + k0 + lseg*4);
        float4 bv = *(const float4*)(qw + (size_t)(n0 + lrow)*QDIM + k0 + lseg*4);
        __syncthreads();
        As[lseg*4+0][lrow]=av.x; As[lseg*4+1][lrow]=av.y;
        As[lseg*4+2][lrow]=av.z; As[lseg*4+3][lrow]=av.w;
        Bs[lseg*4+0][lrow]=bv.x; Bs[lseg*4+1][lrow]=bv.y;
        Bs[lseg*4+2][lrow]=bv.z; Bs[lseg*4+3][lrow]=bv.w;
        __syncthreads();
#pragma unroll
        for (int k = 0; k < BK; k++) {
            float a[4], b[4];
            *(float4*)a = *(float4*)&As[k][ty*4];
            *(float4*)b = *(float4*)&Bs[k][tx*4];
#pragma unroll
            for (int i = 0; i < 4; i++)
#pragma unroll
                for (int j = 0; j < 4; j++)
                    acc[i][j] += a[i]*b[j];
        }
    }
#pragma unroll
    for (int i = 0; i < 4; i++) {
        int gm = m0 + ty*4 + i;
        if (gm >= MROWS) continue;
        int b = gm / NFQ, f = gm % NFQ;
#pragma unroll
        for (int j = 0; j < 4; j++) {
            int e = n0 + tx*4 + j;
            int n = e >> 6, c = e & 63;
            float x = (acc[i][j] + qb[e]) * NORMF;
            __nv_bfloat16 h, l; split_bf16(x, h, l);
            size_t o = (((size_t)(b*NHEADS + n))*NFQ + f)*HD + c;
            g_qht_hi[o] = h; g_qht_lo[o] = l;
        }
    }
}

// ============================================================
// kproj HMMA (3-stage pipeline, R7 structure)
// grid (50 p, 4 e, 4 b), 256 thr
// ============================================================
__global__ void __launch_bounds__(256, 2) kproj_mma_kernel(const float* __restrict__ kb) {
    extern __shared__ char smem[];
    uint32_t sb = smem_u32(smem);
    int t = threadIdx.x, lane = t & 31, w = t >> 5, wm = w >> 2, wn = w & 3;
    int b = blockIdx.z;
    int e0 = blockIdx.y * 128;
    int p0 = blockIdx.x * 128;

    const __nv_bfloat16* Arow0[3];
    const __nv_bfloat16* Brow0[3];
    {
        const __nv_bfloat16* Apass[3] = { g_kw_hi, g_kw_lo, g_kw_hi };
        const __nv_bfloat16* Bpass[3] = { g_kt_hi, g_kt_hi, g_kt_lo };
#pragma unroll
        for (int pss = 0; pss < 3; pss++) {
            Arow0[pss] = Apass[pss] + (size_t)e0*QDIM;
            Brow0[pss] = Bpass[pss] + ((size_t)b*NPIX + p0)*QDIM;
        }
    }

    float acc[4][4][4] = {};
    const int ITERS = 24;   // 3 passes * 8 chunks of 64

    load_tile64(sb + STG(0),          Arow0[0], QDIM, 0, t, 128);
    load_tile64(sb + STG(0) + 16384u, Brow0[0], QDIM, 0, t, 128);
    CP_COMMIT();
    load_tile64(sb + STG(1),          Arow0[0], QDIM, 64, t, 128);
    load_tile64(sb + STG(1) + 16384u, Brow0[0], QDIM, 64, t, 128);
    CP_COMMIT();

    int stage = 0, nstage = 2;
    for (int it = 0; it < ITERS; it++) {
        if (it == ITERS - 1) { CP_WAIT0(); } else { CP_WAIT1(); }
        __syncthreads();
        if (it + 2 < ITERS) {
            int pss = (it+2) >> 3, k0 = ((it+2) & 7) * 64;
            load_tile64(sb + STG(nstage),          Arow0[pss], QDIM, k0, t, 128);
            load_tile64(sb + STG(nstage) + 16384u, Brow0[pss], QDIM, k0, t, 128);
            CP_COMMIT();
        }
        compute_chunk(sb + STG(stage), sb + STG(stage) + 16384u, wm, wn, lane, acc);
        stage = (stage + 1 == 3) ? 0 : stage + 1;
        nstage = (nstage + 1 == 3) ? 0 : nstage + 1;
    }
    __syncthreads();   // protect C overlay (aliases stage buffers)

    float* Cs = (float*)(smem + C_OFF);
    float* kbs = (float*)(smem + KB_OFF);
    if (t < 128) kbs[t] = kb[e0 + t];
    __syncthreads();
#pragma unroll
    for (int mf = 0; mf < 4; mf++) {
        int e = wm*64 + mf*16 + (lane >> 2);
        float b0 = kbs[e], b1 = kbs[e + 8];
#pragma unroll
        for (int nf = 0; nf < 4; nf++) {
            int p = wn*32 + nf*8 + (lane & 3)*2;
            Cs[e*132 + p]       = acc[mf][nf][0] + b0;
            Cs[e*132 + p + 1]   = acc[mf][nf][1] + b0;
            Cs[(e+8)*132 + p]   = acc[mf][nf][2] + b1;
            Cs[(e+8)*132 + p+1] = acc[mf][nf][3] + b1;
        }
    }
    __syncthreads();
    {
        int pl = t & 127, hd = t >> 7;
        size_t rowbase = (((size_t)(b*NHEADS) + blockIdx.y*2 + hd)*NPIX + p0 + pl)*HD;
#pragma unroll
        for (int c8 = 0; c8 < 8; c8++) {
            __align__(16) __nv_bfloat16 h8[8];
            __align__(16) __nv_bfloat16 l8[8];
#pragma unroll
            for (int j = 0; j < 8; j++) {
                float x = Cs[(hd*64 + c8*8 + j)*132 + pl];
                split_bf16(x, h8[j], l8[j]);
            }
            *(uint4*)(g_kpt_hi + rowbase + c8*8) = *(uint4*)h8;
            *(uint4*)(g_kpt_lo + rowbase + c8*8) = *(uint4*)l8;
        }
    }
}

// ============================================================
// scores HMMA (R7 mainloop): writes exp(S - blockmax) (masked -> 0)
// + per-block (blockmax, sumexp).  grid (50 p, 3 f, 32 bh)
// ============================================================
__global__ void __launch_bounds__(256, 2) scores_mma_kernel(const int* __restrict__ mask,
                                                            float* __restrict__ out) {
    extern __shared__ char smem[];
    uint32_t sb = smem_u32(smem);
    int t = threadIdx.x, lane = t & 31, w = t >> 5, wm = w >> 2, wn = w & 3;
    int bh = blockIdx.z;
    int b = bh >> 3, n = bh & 7;
    int m0 = blockIdx.y * 128;
    int p0 = blockIdx.x * 128;

    int* mS = (int*)(smem + MK_OFF);
    if (t < 128) mS[t] = mask[(size_t)b*NPIX + p0 + t];

    int nrows = NFQ - m0; if (nrows > 128) nrows = 128;
    const __nv_bfloat16* Arow0[3] = {
        g_qht_hi + (((size_t)(b*NHEADS + n))*NFQ + m0)*HD,
        g_qht_lo + (((size_t)(b*NHEADS + n))*NFQ + m0)*HD,
        g_qht_hi + (((size_t)(b*NHEADS + n))*NFQ + m0)*HD };
    const __nv_bfloat16* Brow0[3] = {
        g_kpt_hi + (((size_t)(b*NHEADS + n))*NPIX + p0)*HD,
        g_kpt_hi + (((size_t)(b*NHEADS + n))*NPIX + p0)*HD,
        g_kpt_lo + (((size_t)(b*NHEADS + n))*NPIX + p0)*HD };

    float acc[4][4][4] = {};
    const int ITERS = 3;
    load_tile64(sb + STG(0),          Arow0[0], HD, 0, t, nrows);
    load_tile64(sb + STG(0) + 16384u, Brow0[0], HD, 0, t, 128);
    CP_COMMIT();
    load_tile64(sb + STG(1),          Arow0[1], HD, 0, t, nrows);
    load_tile64(sb + STG(1) + 16384u, Brow0[1], HD, 0, t, 128);
    CP_COMMIT();
    for (int it = 0; it < ITERS; it++) {
        if (it == ITERS - 1) { CP_WAIT0(); } else { CP_WAIT1(); }
        __syncthreads();
        if (it + 2 < ITERS) {
            load_tile64(sb + STG(2),          Arow0[2], HD, 0, t, nrows);
            load_tile64(sb + STG(2) + 16384u, Brow0[2], HD, 0, t, 128);
            CP_COMMIT();
        }
        compute_chunk(sb + STG(it), sb + STG(it) + 16384u, wm, wn, lane, acc);
    }

    // ---- epilogue pass 1: per-thread max over unmasked elements ----
    float* rm = (float*)(smem + RM_OFF);
    float* rs = (float*)(smem + RS_OFF);
    float tmax = -INFINITY;
#pragma unroll
    for (int mf = 0; mf < 4; mf++) {
        int fl = wm*64 + mf*16 + (lane >> 2);
#pragma unroll
        for (int half = 0; half < 2; half++) {
            int fg = m0 + fl + half*8;
            if (fg < NFQ) {
#pragma unroll
                for (int nf = 0; nf < 4; nf++) {
                    int nc = wn*32 + nf*8 + (lane & 3)*2;
                    if (!mS[nc])   tmax = fmaxf(tmax, acc[mf][nf][half*2]);
                    if (!mS[nc+1]) tmax = fmaxf(tmax, acc[mf][nf][half*2+1]);
                }
            }
        }
    }
    rm[t] = tmax;
    __syncthreads();
    for (int s = 128; s > 0; s >>= 1) {
        if (t < s) rm[t] = fmaxf(rm[t], rm[t+s]);
        __syncthreads();
    }
    float bmax = rm[0];
    float base = (bmax > -1e37f) ? bmax : 0.f;

    // ---- pass 2: exp, store, sum ----
    size_t obase = (size_t)b*OROWS*NPIX;
    float tsum = 0.f;
#pragma unroll
    for (int mf = 0; mf < 4; mf++) {
        int fl = wm*64 + mf*16 + (lane >> 2);
#pragma unroll
        for (int half = 0; half < 2; half++) {
            int fg = m0 + fl + half*8;
            if (fg < NFQ) {
                size_t rowb = obase + ((size_t)fg*NHEADS + n)*NPIX + p0;
#pragma unroll
                for (int nf = 0; nf < 4; nf++) {
                    int nc = wn*32 + nf*8 + (lane & 3)*2;
                    float e0 = mS[nc]   ? 0.f : __expf(acc[mf][nf][half*2]   - base);
                    float e1 = mS[nc+1] ? 0.f : __expf(acc[mf][nf][half*2+1] - base);
                    *(float2*)(out + rowb + nc) = make_float2(e0, e1);
                    tsum += e0 + e1;
                }
            }
        }
    }
    rs[t] = tsum;
    __syncthreads();
    for (int s = 128; s > 0; s >>= 1) {
        if (t < s) rs[t] += rs[t+s];
        __syncthreads();
    }
    if (t == 0) {
        int pidx = (int)blockIdx.z*150 + (int)blockIdx.y*50 + (int)blockIdx.x;
        g_pmax[pidx] = bmax;
        g_psum[pidx] = rs[0];
    }
}

// ============================================================
// combine: per-batch (M, Z) then per-block scale = exp(bmax-M)/Z
// ============================================================
__global__ void combine_kernel() {
    __shared__ float rm[256];
    __shared__ float rs[256];
    __shared__ float sM, sIZ;
    int b = blockIdx.x, t = threadIdx.x;
    float m = -INFINITY, s = 0.f;
    for (int i = t; i < CBLK_PER_BATCH; i += 256) {
        float m2 = g_pmax[b*CBLK_PER_BATCH + i];
        float s2 = g_psum[b*CBLK_PER_BATCH + i];
        float M = fmaxf(m, m2);
        float ns = 0.f;
        if (m  > -1e37f) ns += s  * __expf(m  - M);
        if (m2 > -1e37f) ns += s2 * __expf(m2 - M);
        m = M; s = ns;
    }
    rm[t] = m; rs[t] = s;
    __syncthreads();
    for (int st = 128; st > 0; st >>= 1) {
        if (t < st) {
            float m1 = rm[t], s1v = rs[t];
            float m2 = rm[t+st], s2v = rs[t+st];
            float M = fmaxf(m1, m2);
            float sum = 0.f;
            if (m1 > -1e37f) sum += s1v * __expf(m1 - M);
            if (m2 > -1e37f) sum += s2v * __expf(m2 - M);
            rm[t] = M; rs[t] = sum;
        }
        __syncthreads();
    }
    if (t == 0) { sM = rm[0]; sIZ = 1.0f / rs[0]; }
    __syncthreads();
    float M = sM, iz = sIZ;
    for (int i = t; i < CBLK_PER_BATCH; i += 256) {
        float pm = g_pmax[b*CBLK_PER_BATCH + i];
        g_bscale[b*CBLK_PER_BATCH + i] = (pm > -1e37f) ? __expf(pm - M) * iz : 0.f;
    }
}

// ============================================================
// normalize in place: pure per-block scale multiply (no exp)
// ============================================================
__global__ void norm_kernel(float* __restrict__ out) {
    const int VPB4 = (OROWS*NPIX) / 4;   // 3,840,000 float4 per batch
    const int NP4  = NPIX / 4;           // 1600
    const int NV   = NBATCH * VPB4;
    float4* o = (float4*)out;
    for (int i = blockIdx.x*blockDim.x + threadIdx.x; i < NV;
         i += gridDim.x*blockDim.x) {
        int b   = i / VPB4;
        int rem = i - b*VPB4;
        int r   = rem / NP4;             // row = f*8 + n, 0..2399
        int p4  = rem - r*NP4;           // float4 col; p>>7 == p4>>5
        int pidx = ((b*NHEADS + (r & 7))*3 + (r >> 10))*50 + (p4 >> 5);
        float s = g_bscale[pidx];
        float4 v = o[i];
        v.x *= s; v.y *= s; v.z *= s; v.w *= s;
        o[i] = v;
    }
}

// ============================================================
extern "C" void kernel_launch(void* const* d_in, const int* in_sizes, int n_in,
                              void* d_out, int out_size) {
    const float* q    = (const float*)d_in[0];
    const float* k    = (const float*)d_in[1];
    const int*   mask = (const int*)  d_in[2];
    const float* qw   = (const float*)d_in[3];
    const float* qb   = (const float*)d_in[4];
    const float* kw   = (const float*)d_in[5];
    const float* kb   = (const float*)d_in[6];
    float* out = (float*)d_out;

    cudaFuncSetAttribute(kproj_mma_kernel,  cudaFuncAttributeMaxDynamicSharedMemorySize, SMEM_SZ);
    cudaFuncSetAttribute(scores_mma_kernel, cudaFuncAttributeMaxDynamicSharedMemorySize, SMEM_SZ);

    kwconv_kernel <<<256, 256>>>(kw);
    kconv_kernel  <<<dim3(200, 16, 4), dim3(32, 8)>>>(k);
    qproj_kernel  <<<dim3(8, 19), 256>>>(q, qw, qb);
    kproj_mma_kernel <<<dim3(50, 4, 4),  256, SMEM_SZ>>>(kb);
    scores_mma_kernel<<<dim3(50, 3, 32), 256, SMEM_SZ>>>(mask, out);
    combine_kernel<<<4, 256>>>();
    norm_kernel   <<<2048, 256>>>(out);
}

// round 11
// speedup vs baseline: 1.3332x; 1.2217x over previous
#include <cuda_runtime.h>
#include <cuda_bf16.h>
#include <stdint.h>
#include <math.h>

#define NBATCH 4
#define NFQ    300
#define QDIM   512
#define HIDDEN 512
#define NHEADS 8
#define HD     64
#define NPIX   6400
#define NORMF  0.125f
#define MROWS  (NBATCH*NFQ)          // 1200
#define OROWS  (NFQ*NHEADS)          // 2400
#define CBLK_PER_BATCH 1200          // 8 heads * 3 mtiles * 50 ntiles
#define TILE_B 16384                 // one operand tile: 128 rows x 64 bf16, swizzled
#define TILE_E 8192                  // elements per tile

// ---------------- static device scratch (pre-swizzled tile layouts) ----------------
// kw tiles:   [etile 4][kchunk 8] of 16KB
__device__ __align__(128) __nv_bfloat16 g_kwT_hi[4*8*TILE_E];
__device__ __align__(128) __nv_bfloat16 g_kwT_lo[4*8*TILE_E];
// kt tiles:   [b 4][ptile 50][kchunk 8]
__device__ __align__(128) __nv_bfloat16 g_ktT_hi[(size_t)4*50*8*TILE_E];
__device__ __align__(128) __nv_bfloat16 g_ktT_lo[(size_t)4*50*8*TILE_E];
// qht tiles:  [b 4][n 8][ftile 3]
__device__ __align__(128) __nv_bfloat16 g_qhtT_hi[4*8*3*TILE_E];
__device__ __align__(128) __nv_bfloat16 g_qhtT_lo[4*8*3*TILE_E];
// kpt tiles:  [b 4][head 8][ptile 50]
__device__ __align__(128) __nv_bfloat16 g_kptT_hi[(size_t)4*8*50*TILE_E];
__device__ __align__(128) __nv_bfloat16 g_kptT_lo[(size_t)4*8*50*TILE_E];
__device__ float g_pmax[NBATCH*CBLK_PER_BATCH];
__device__ float g_psum[NBATCH*CBLK_PER_BATCH];
__device__ float g_bscale[NBATCH*CBLK_PER_BATCH];

// ---------------- smem layout ----------------
#define STAGE_SZ 32768u
#define STG(s)   ((uint32_t)(s) * STAGE_SZ)
#define C_OFF  0u
#define KB_OFF 98304u
#define RM_OFF 98304u
#define RS_OFF 99328u
#define MK_OFF 100352u
#define MB_OFF 100864u                  // 3 mbarriers x 8B
#define SMEM_SZ 100896u

// ---------------- ptx helpers ----------------
__device__ __forceinline__ uint32_t smem_u32(const void* p) {
    uint32_t a;
    asm("{ .reg .u64 t; cvta.to.shared.u64 t, %1; cvt.u32.u64 %0, t; }" : "=r"(a) : "l"(p));
    return a;
}
__device__ __forceinline__ void bulk_cp(uint32_t dst, const void* src, uint32_t bytes,
                                        uint32_t mbar) {
    asm volatile("cp.async.bulk.shared::cta.global.mbarrier::complete_tx::bytes "
                 "[%0], [%1], %2, [%3];"
                 :: "r"(dst), "l"(src), "r"(bytes), "r"(mbar) : "memory");
}
#define MBINIT(a,c) asm volatile("mbarrier.init.shared.b64 [%0], %1;" :: "r"(a), "r"(c) : "memory")
#define MBEXPECT(a,tx) asm volatile("mbarrier.arrive.expect_tx.shared.b64 _, [%0], %1;" :: "r"(a), "r"(tx) : "memory")
#define MBAR_WAIT(mbar, parity) do { \
    uint32_t _m = (mbar); uint32_t _p = (parity); uint32_t _done; \
    asm volatile("{\n\t.reg .pred p;\n\t" \
        "mbarrier.try_wait.parity.acquire.cta.shared::cta.b64 p, [%1], %2;\n\t" \
        "selp.b32 %0, 1, 0, p;\n\t}" : "=r"(_done) : "r"(_m), "r"(_p) : "memory"); \
    if (!_done) { \
        asm volatile("{\n\t.reg .pred P1;\n\t" \
            "WL_%=:\n\t" \
            "mbarrier.try_wait.parity.acquire.cta.shared::cta.b64 P1, [%0], %1, 0x989680;\n\t" \
            "@P1 bra.uni WD_%=;\n\t" \
            "bra.uni WL_%=;\n\t" \
            "WD_%=:\n\t}" :: "r"(_m), "r"(_p) : "memory"); \
    } \
} while(0)

__device__ __forceinline__ void ldm_x4(uint32_t& r0, uint32_t& r1, uint32_t& r2, uint32_t& r3,
                                       uint32_t addr) {
    asm volatile("ldmatrix.sync.aligned.m8n8.x4.shared.b16 {%0,%1,%2,%3}, [%4];"
                 : "=r"(r0), "=r"(r1), "=r"(r2), "=r"(r3) : "r"(addr));
}
__device__ __forceinline__ void mma_bf16(float* c, uint32_t a0, uint32_t a1, uint32_t a2,
                                         uint32_t a3, uint32_t b0, uint32_t b1) {
    asm volatile("mma.sync.aligned.m16n8k16.row.col.f32.bf16.bf16.f32 "
        "{%0,%1,%2,%3}, {%4,%5,%6,%7}, {%8,%9}, {%0,%1,%2,%3};"
        : "+f"(c[0]), "+f"(c[1]), "+f"(c[2]), "+f"(c[3])
        : "r"(a0), "r"(a1), "r"(a2), "r"(a3), "r"(b0), "r"(b1));
}
__device__ __forceinline__ uint32_t sw128(uint32_t off) { return off ^ ((off >> 3) & 0x70); }

__device__ __forceinline__ void split_bf16(float x, __nv_bfloat16& h, __nv_bfloat16& l) {
    h = __float2bfloat16(x);
    l = __float2bfloat16(x - __bfloat162float(h));
}

// ---- one 64-wide K chunk of 128x128 HMMA (warp tile 64x32) ----
__device__ __forceinline__ void compute_chunk(uint32_t aBase, uint32_t bBase,
                                              int wm, int wn, int lane,
                                              float acc[4][4][4]) {
#pragma unroll
    for (int kk = 0; kk < 64; kk += 16) {
        uint32_t a[4][4];
#pragma unroll
        for (int mf = 0; mf < 4; mf++) {
            int row  = wm*64 + mf*16 + (lane & 15);
            int kcol = kk + ((lane >> 4) << 3);
            uint32_t off = sw128((uint32_t)(row*128 + kcol*2));
            ldm_x4(a[mf][0], a[mf][1], a[mf][2], a[mf][3], aBase + off);
        }
        uint32_t b[4][2];
#pragma unroll
        for (int g = 0; g < 2; g++) {
            int nrow = wn*32 + g*16 + ((lane >> 4) << 3) + (lane & 7);
            int kcol = kk + (((lane >> 3) & 1) << 3);
            uint32_t off = sw128((uint32_t)(nrow*128 + kcol*2));
            uint32_t r0, r1, r2, r3;
            ldm_x4(r0, r1, r2, r3, bBase + off);
            b[g*2][0] = r0; b[g*2][1] = r1; b[g*2+1][0] = r2; b[g*2+1][1] = r3;
        }
#pragma unroll
        for (int mf = 0; mf < 4; mf++)
#pragma unroll
            for (int nf = 0; nf < 4; nf++)
                mma_bf16(acc[mf][nf], a[mf][0], a[mf][1], a[mf][2], a[mf][3],
                         b[nf][0], b[nf][1]);
    }
}

// ============================================================
// convert kw -> pre-swizzled tiles (hi/lo). thread per 8 d.
// ============================================================
__global__ void kwconv_kernel(const float* __restrict__ kw) {
    int n8 = HIDDEN*QDIM/8;
    for (int i = blockIdx.x*blockDim.x + threadIdx.x; i < n8; i += gridDim.x*blockDim.x) {
        int e = i >> 6, dg = i & 63;
        int d0 = dg * 8;
        __align__(16) __nv_bfloat16 h8[8];
        __align__(16) __nv_bfloat16 l8[8];
#pragma unroll
        for (int j = 0; j < 8; j++)
            split_bf16(kw[(size_t)e*QDIM + d0 + j], h8[j], l8[j]);
        uint32_t tile = (uint32_t)(e >> 7)*8 + (d0 >> 6);
        uint32_t off = tile*TILE_B + sw128((uint32_t)((e & 127)*128 + (d0 & 63)*2));
        *(uint4*)((char*)g_kwT_hi + off) = *(uint4*)h8;
        *(uint4*)((char*)g_kwT_lo + off) = *(uint4*)l8;
    }
}

// ============================================================
// convert + transpose k -> pre-swizzled kt tiles.
// grid (200 p32, 8 d64, 4 b), block (32,8)
// ============================================================
__global__ void kconv_kernel(const float* __restrict__ kin) {
    __shared__ float tile[64][33];
    int b = blockIdx.z;
    int p0 = blockIdx.x*32, d0 = blockIdx.y*64;
    int tx = threadIdx.x, ty = threadIdx.y;
    const float* src = kin + ((size_t)b*QDIM + d0)*NPIX + p0;
#pragma unroll
    for (int i = 0; i < 8; i++)
        tile[ty + i*8][tx] = src[(size_t)(ty + i*8)*NPIX + tx];
    __syncthreads();
    int tid = ty*32 + tx;
    int pl = tid >> 3, dg = tid & 7;          // pl 0..31, dg 0..7 (8 d each)
    __align__(16) __nv_bfloat16 h8[8];
    __align__(16) __nv_bfloat16 l8[8];
#pragma unroll
    for (int j = 0; j < 8; j++)
        split_bf16(tile[dg*8 + j][pl], h8[j], l8[j]);
    int p = p0 + pl;
    uint32_t tl = (uint32_t)((b*50 + (p >> 7))*8 + (d0 >> 6));
    uint32_t off = tl*TILE_B + sw128((uint32_t)((p & 127)*128 + dg*16));
    *(uint4*)((char*)g_ktT_hi + off) = *(uint4*)h8;
    *(uint4*)((char*)g_ktT_lo + off) = *(uint4*)l8;
}

// ============================================================
// q projection (SIMT) -> pre-swizzled qht tiles
// ============================================================
__global__ void qproj_kernel(const float* __restrict__ q,
                             const float* __restrict__ qw,
                             const float* __restrict__ qb) {
    const int BM = 64, BN = 64, BK = 16;
    __shared__ float As[BK][BM];
    __shared__ float Bs[BK][BN];
    int t  = threadIdx.x;
    int tx = t & 15, ty = t >> 4;
    int m0 = blockIdx.y * BM;
    int n0 = blockIdx.x * BN;
    int lrow = t >> 2, lseg = t & 3;

    float acc[4][4] = {};
    for (int k0 = 0; k0 < QDIM; k0 += BK) {
        float4 av = make_float4(0.f, 0.f, 0.f, 0.f);
        int gm = m0 + lrow;
        if (gm < MROWS)
            av = *(const float4*)(q + (size_t)gm*QDIM + k0 + lseg*4);
        float4 bv = *(const float4*)(qw + (size_t)(n0 + lrow)*QDIM + k0 + lseg*4);
        __syncthreads();
        As[lseg*4+0][lrow]=av.x; As[lseg*4+1][lrow]=av.y;
        As[lseg*4+2][lrow]=av.z; As[lseg*4+3][lrow]=av.w;
        Bs[lseg*4+0][lrow]=bv.x; Bs[lseg*4+1][lrow]=bv.y;
        Bs[lseg*4+2][lrow]=bv.z; Bs[lseg*4+3][lrow]=bv.w;
        __syncthreads();
#pragma unroll
        for (int k = 0; k < BK; k++) {
            float a[4], b[4];
            *(float4*)a = *(float4*)&As[k][ty*4];
            *(float4*)b = *(float4*)&Bs[k][tx*4];
#pragma unroll
            for (int i = 0; i < 4; i++)
#pragma unroll
                for (int j = 0; j < 4; j++)
                    acc[i][j] += a[i]*b[j];
        }
    }
    int n = n0 >> 6;                       // BN=64 => single head per block
#pragma unroll
    for (int i = 0; i < 4; i++) {
        int gm = m0 + ty*4 + i;
        if (gm >= MROWS) continue;
        int b = gm / NFQ, f = gm % NFQ;
        __align__(8) __nv_bfloat16 h4[4];
        __align__(8) __nv_bfloat16 l4[4];
#pragma unroll
        for (int j = 0; j < 4; j++) {
            int e = n0 + tx*4 + j;
            float x = (acc[i][j] + qb[e]) * NORMF;
            split_bf16(x, h4[j], l4[j]);
        }
        uint32_t tl = (uint32_t)((b*NHEADS + n)*3 + (f >> 7));
        uint32_t off = tl*TILE_B + sw128((uint32_t)((f & 127)*128 + tx*8));
        *(uint2*)((char*)g_qhtT_hi + off) = *(uint2*)h4;
        *(uint2*)((char*)g_qhtT_lo + off) = *(uint2*)l4;
    }
}

// ============================================================
// kproj HMMA: bulk-DMA 3-stage pipeline.  grid (50 p, 4 e, 4 b), 256 thr
// ============================================================
__global__ void __launch_bounds__(256, 2) kproj_mma_kernel(const float* __restrict__ kb) {
    extern __shared__ char smem[];
    uint32_t sb = smem_u32(smem);
    int t = threadIdx.x, lane = t & 31, w = t >> 5, wm = w >> 2, wn = w & 3;
    int b = blockIdx.z;
    int e0 = blockIdx.y * 128;
    int p0 = blockIdx.x * 128;

    const char* Ap[3] = {
        (const char*)g_kwT_hi + (size_t)blockIdx.y*8*TILE_B,
        (const char*)g_kwT_lo + (size_t)blockIdx.y*8*TILE_B,
        (const char*)g_kwT_hi + (size_t)blockIdx.y*8*TILE_B };
    const char* Bp[3] = {
        (const char*)g_ktT_hi + (size_t)(b*50 + blockIdx.x)*8*TILE_B,
        (const char*)g_ktT_hi + (size_t)(b*50 + blockIdx.x)*8*TILE_B,
        (const char*)g_ktT_lo + (size_t)(b*50 + blockIdx.x)*8*TILE_B };

    if (t == 0) {
        MBINIT(sb + MB_OFF + 0, 1);
        MBINIT(sb + MB_OFF + 8, 1);
        MBINIT(sb + MB_OFF + 16, 1);
    }
    __syncthreads();

    const int ITERS = 24;
    if (t == 0) {
#pragma unroll
        for (int it = 0; it < 2; it++) {
            int pss = it >> 3, kc = it & 7, st = it % 3;
            MBEXPECT(sb + MB_OFF + st*8, 32768u);
            bulk_cp(sb + STG(st),          Ap[pss] + (size_t)kc*TILE_B, TILE_B, sb + MB_OFF + st*8);
            bulk_cp(sb + STG(st) + 16384u, Bp[pss] + (size_t)kc*TILE_B, TILE_B, sb + MB_OFF + st*8);
        }
    }

    float acc[4][4][4] = {};
    for (int it = 0; it < ITERS; it++) {
        int st = it % 3;
        MBAR_WAIT(sb + MB_OFF + st*8, (uint32_t)((it/3) & 1));
        __syncthreads();
        if (t == 0 && it + 2 < ITERS) {
            int it2 = it + 2;
            int pss = it2 >> 3, kc = it2 & 7, s2 = it2 % 3;
            MBEXPECT(sb + MB_OFF + s2*8, 32768u);
            bulk_cp(sb + STG(s2),          Ap[pss] + (size_t)kc*TILE_B, TILE_B, sb + MB_OFF + s2*8);
            bulk_cp(sb + STG(s2) + 16384u, Bp[pss] + (size_t)kc*TILE_B, TILE_B, sb + MB_OFF + s2*8);
        }
        compute_chunk(sb + STG(st), sb + STG(st) + 16384u, wm, wn, lane, acc);
    }
    __syncthreads();   // protect C overlay (aliases stage buffers)

    float* Cs = (float*)(smem + C_OFF);
    float* kbs = (float*)(smem + KB_OFF);
    if (t < 128) kbs[t] = kb[e0 + t];
    __syncthreads();
#pragma unroll
    for (int mf = 0; mf < 4; mf++) {
        int e = wm*64 + mf*16 + (lane >> 2);
        float b0 = kbs[e], b1 = kbs[e + 8];
#pragma unroll
        for (int nf = 0; nf < 4; nf++) {
            int p = wn*32 + nf*8 + (lane & 3)*2;
            Cs[e*132 + p]       = acc[mf][nf][0] + b0;
            Cs[e*132 + p + 1]   = acc[mf][nf][1] + b0;
            Cs[(e+8)*132 + p]   = acc[mf][nf][2] + b1;
            Cs[(e+8)*132 + p+1] = acc[mf][nf][3] + b1;
        }
    }
    __syncthreads();
    {
        int pl = t & 127, hd = t >> 7;
        int head = blockIdx.y*2 + hd;
        uint32_t tl = (uint32_t)((b*NHEADS + head)*50 + blockIdx.x);
#pragma unroll
        for (int c8 = 0; c8 < 8; c8++) {
            __align__(16) __nv_bfloat16 h8[8];
            __align__(16) __nv_bfloat16 l8[8];
#pragma unroll
            for (int j = 0; j < 8; j++) {
                float x = Cs[(hd*64 + c8*8 + j)*132 + pl];
                split_bf16(x, h8[j], l8[j]);
            }
            uint32_t off = tl*TILE_B + sw128((uint32_t)(pl*128 + c8*16));
            *(uint4*)((char*)g_kptT_hi + off) = *(uint4*)h8;
            *(uint4*)((char*)g_kptT_lo + off) = *(uint4*)l8;
        }
    }
}

// ============================================================
// scores HMMA: bulk-DMA, writes exp(S - blockmax) + block stats.
// grid (50 p, 3 f, 32 bh)
// ============================================================
__global__ void __launch_bounds__(256, 2) scores_mma_kernel(const int* __restrict__ mask,
                                                            float* __restrict__ out) {
    extern __shared__ char smem[];
    uint32_t sb = smem_u32(smem);
    int t = threadIdx.x, lane = t & 31, w = t >> 5, wm = w >> 2, wn = w & 3;
    int bh = blockIdx.z;
    int b = bh >> 3, n = bh & 7;
    int m0 = blockIdx.y * 128;
    int p0 = blockIdx.x * 128;

    int* mS = (int*)(smem + MK_OFF);
    if (t < 128) mS[t] = mask[(size_t)b*NPIX + p0 + t];

    const char* qtile_hi = (const char*)g_qhtT_hi + (size_t)((b*NHEADS + n)*3 + blockIdx.y)*TILE_B;
    const char* qtile_lo = (const char*)g_qhtT_lo + (size_t)((b*NHEADS + n)*3 + blockIdx.y)*TILE_B;
    const char* ktile_hi = (const char*)g_kptT_hi + (size_t)((b*NHEADS + n)*50 + blockIdx.x)*TILE_B;
    const char* ktile_lo = (const char*)g_kptT_lo + (size_t)((b*NHEADS + n)*50 + blockIdx.x)*TILE_B;
    const char* Ap[3] = { qtile_hi, qtile_lo, qtile_hi };
    const char* Bp[3] = { ktile_hi, ktile_hi, ktile_lo };

    if (t == 0) {
        MBINIT(sb + MB_OFF + 0, 1);
        MBINIT(sb + MB_OFF + 8, 1);
        MBINIT(sb + MB_OFF + 16, 1);
    }
    __syncthreads();
    if (t == 0) {
#pragma unroll
        for (int it = 0; it < 2; it++) {
            MBEXPECT(sb + MB_OFF + it*8, 32768u);
            bulk_cp(sb + STG(it),          Ap[it], TILE_B, sb + MB_OFF + it*8);
            bulk_cp(sb + STG(it) + 16384u, Bp[it], TILE_B, sb + MB_OFF + it*8);
        }
    }

    float acc[4][4][4] = {};
    for (int it = 0; it < 3; it++) {
        MBAR_WAIT(sb + MB_OFF + it*8, 0u);
        __syncthreads();
        if (t == 0 && it == 0) {
            MBEXPECT(sb + MB_OFF + 16, 32768u);
            bulk_cp(sb + STG(2),          Ap[2], TILE_B, sb + MB_OFF + 16);
            bulk_cp(sb + STG(2) + 16384u, Bp[2], TILE_B, sb + MB_OFF + 16);
        }
        compute_chunk(sb + STG(it), sb + STG(it) + 16384u, wm, wn, lane, acc);
    }

    // ---- epilogue pass 1: per-thread max over unmasked elements ----
    float* rm = (float*)(smem + RM_OFF);
    float* rs = (float*)(smem + RS_OFF);
    float tmax = -INFINITY;
#pragma unroll
    for (int mf = 0; mf < 4; mf++) {
        int fl = wm*64 + mf*16 + (lane >> 2);
#pragma unroll
        for (int half = 0; half < 2; half++) {
            int fg = m0 + fl + half*8;
            if (fg < NFQ) {
#pragma unroll
                for (int nf = 0; nf < 4; nf++) {
                    int nc = wn*32 + nf*8 + (lane & 3)*2;
                    if (!mS[nc])   tmax = fmaxf(tmax, acc[mf][nf][half*2]);
                    if (!mS[nc+1]) tmax = fmaxf(tmax, acc[mf][nf][half*2+1]);
                }
            }
        }
    }
    rm[t] = tmax;
    __syncthreads();
    for (int s = 128; s > 0; s >>= 1) {
        if (t < s) rm[t] = fmaxf(rm[t], rm[t+s]);
        __syncthreads();
    }
    float bmax = rm[0];
    float base = (bmax > -1e37f) ? bmax : 0.f;

    // ---- pass 2: exp, store, sum ----
    size_t obase = (size_t)b*OROWS*NPIX;
    float tsum = 0.f;
#pragma unroll
    for (int mf = 0; mf < 4; mf++) {
        int fl = wm*64 + mf*16 + (lane >> 2);
#pragma unroll
        for (int half = 0; half < 2; half++) {
            int fg = m0 + fl + half*8;
            if (fg < NFQ) {
                size_t rowb = obase + ((size_t)fg*NHEADS + n)*NPIX + p0;
#pragma unroll
                for (int nf = 0; nf < 4; nf++) {
                    int nc = wn*32 + nf*8 + (lane & 3)*2;
                    float e0 = mS[nc]   ? 0.f : __expf(acc[mf][nf][half*2]   - base);
                    float e1 = mS[nc+1] ? 0.f : __expf(acc[mf][nf][half*2+1] - base);
                    *(float2*)(out + rowb + nc) = make_float2(e0, e1);
                    tsum += e0 + e1;
                }
            }
        }
    }
    rs[t] = tsum;
    __syncthreads();
    for (int s = 128; s > 0; s >>= 1) {
        if (t < s) rs[t] += rs[t+s];
        __syncthreads();
    }
    if (t == 0) {
        int pidx = (int)blockIdx.z*150 + (int)blockIdx.y*50 + (int)blockIdx.x;
        g_pmax[pidx] = bmax;
        g_psum[pidx] = rs[0];
    }
}

// ============================================================
// combine: per-batch (M, Z) then per-block scale = exp(bmax-M)/Z
// ============================================================
__global__ void combine_kernel() {
    __shared__ float rm[256];
    __shared__ float rs[256];
    __shared__ float sM, sIZ;
    int b = blockIdx.x, t = threadIdx.x;
    float m = -INFINITY, s = 0.f;
    for (int i = t; i < CBLK_PER_BATCH; i += 256) {
        float m2 = g_pmax[b*CBLK_PER_BATCH + i];
        float s2 = g_psum[b*CBLK_PER_BATCH + i];
        float M = fmaxf(m, m2);
        float ns = 0.f;
        if (m  > -1e37f) ns += s  * __expf(m  - M);
        if (m2 > -1e37f) ns += s2 * __expf(m2 - M);
        m = M; s = ns;
    }
    rm[t] = m; rs[t] = s;
    __syncthreads();
    for (int st = 128; st > 0; st >>= 1) {
        if (t < st) {
            float m1 = rm[t], s1v = rs[t];
            float m2 = rm[t+st], s2v = rs[t+st];
            float M = fmaxf(m1, m2);
            float sum = 0.f;
            if (m1 > -1e37f) sum += s1v * __expf(m1 - M);
            if (m2 > -1e37f) sum += s2v * __expf(m2 - M);
            rm[t] = M; rs[t] = sum;
        }
        __syncthreads();
    }
    if (t == 0) { sM = rm[0]; sIZ = 1.0f / rs[0]; }
    __syncthreads();
    float M = sM, iz = sIZ;
    for (int i = t; i < CBLK_PER_BATCH; i += 256) {
        float pm = g_pmax[b*CBLK_PER_BATCH + i];
        g_bscale[b*CBLK_PER_BATCH + i] = (pm > -1e37f) ? __expf(pm - M) * iz : 0.f;
    }
}

// ============================================================
// normalize in place: pure per-block scale multiply (no exp)
// ============================================================
__global__ void norm_kernel(float* __restrict__ out) {
    const int VPB4 = (OROWS*NPIX) / 4;
    const int NP4  = NPIX / 4;
    const int NV   = NBATCH * VPB4;
    float4* o = (float4*)out;
    for (int i = blockIdx.x*blockDim.x + threadIdx.x; i < NV;
         i += gridDim.x*blockDim.x) {
        int b   = i / VPB4;
        int rem = i - b*VPB4;
        int r   = rem / NP4;
        int p4  = rem - r*NP4;
        int pidx = ((b*NHEADS + (r & 7))*3 + (r >> 10))*50 + (p4 >> 5);
        float s = g_bscale[pidx];
        float4 v = o[i];
        v.x *= s; v.y *= s; v.z *= s; v.w *= s;
        o[i] = v;
    }
}

// ============================================================
extern "C" void kernel_launch(void* const* d_in, const int* in_sizes, int n_in,
                              void* d_out, int out_size) {
    const float* q    = (const float*)d_in[0];
    const float* k    = (const float*)d_in[1];
    const int*   mask = (const int*)  d_in[2];
    const float* qw   = (const float*)d_in[3];
    const float* qb   = (const float*)d_in[4];
    const float* kw   = (const float*)d_in[5];
    const float* kb   = (const float*)d_in[6];
    float* out = (float*)d_out;

    cudaFuncSetAttribute(kproj_mma_kernel,  cudaFuncAttributeMaxDynamicSharedMemorySize, SMEM_SZ);
    cudaFuncSetAttribute(scores_mma_kernel, cudaFuncAttributeMaxDynamicSharedMemorySize, SMEM_SZ);

    kwconv_kernel <<<128, 256>>>(kw);
    kconv_kernel  <<<dim3(200, 8, 4), dim3(32, 8)>>>(k);
    qproj_kernel  <<<dim3(8, 19), 256>>>(q, qw, qb);
    kproj_mma_kernel <<<dim3(50, 4, 4),  256, SMEM_SZ>>>(kb);
    scores_mma_kernel<<<dim3(50, 3, 32), 256, SMEM_SZ>>>(mask, out);
    combine_kernel<<<4, 256>>>();
    norm_kernel   <<<2048, 256>>>(out);
}